// round 2
// baseline (speedup 1.0000x reference)
#include <cuda_runtime.h>

#define LEVEL 256
#define NBLK  8
#define HH    1024
#define WW    1024
#define BM    128          // block rows (HH/NBLK)
#define BN    128          // block cols
#define TV    640.0f       // (BM*BN)/LEVEL*THRESH = 16384/256*10

// per-block uint8 mapping tables, stored as float (B=16 max)
__device__ float g_maps[16 * NBLK * NBLK * LEVEL];

// ============================================================================
// Kernel 1: per-block histogram (atomic-free byte counters) + clip + CDF->map
// grid: (64, B), block: 128 threads
// ============================================================================
__global__ __launch_bounds__(128) void hist_maps_kernel(const float* __restrict__ img) {
    // counters: [bin][byte 0..127], byte index = lane*4 + warp
    // word index = bin*32 + lane  ->  bank = lane  (conflict-free)
    // each (warp,lane) owns a distinct byte -> no write races
    __shared__ unsigned char cnt[LEVEL * 128];   // 32 KB
    __shared__ float hs[LEVEL];                  // per-bin counts
    __shared__ float cs[LEVEL];                  // clipped / scanned values
    __shared__ int   wsum[4];

    const int t    = threadIdx.x;       // 0..127
    const int lane = t & 31;
    const int warp = t >> 5;            // 0..3
    const int blk  = blockIdx.x;        // 0..63
    const int b    = blockIdx.y;
    const int bi   = blk >> 3, bj = blk & 7;

    unsigned int* c32 = reinterpret_cast<unsigned int*>(cnt);
    #pragma unroll
    for (int k = 0; k < 64; ++k) c32[t + k * 128] = 0u;   // zero 8192 words
    __syncthreads();

    // ---- accumulate 128x128 region (float4 loads, 32 vecs/row) ----
    const float* base = img + ((size_t)b * HH + (size_t)bi * BM) * WW + bj * BN;
    const int boff = lane * 4 + warp;
    #pragma unroll 4
    for (int k = 0; k < 32; ++k) {
        int idx = k * 128 + t;          // 0..4095 vec index
        int row = idx >> 5;
        int c4  = idx & 31;
        float4 p = *reinterpret_cast<const float4*>(base + (size_t)row * WW + c4 * 4);
        cnt[((int)p.x) * 128 + boff]++;
        cnt[((int)p.y) * 128 + boff]++;
        cnt[((int)p.z) * 128 + boff]++;
        cnt[((int)p.w) * 128 + boff]++;
    }
    __syncthreads();

    // ---- reduce 128 bytes per bin via dp4a (lane-rotated, conflict-free) ----
    #pragma unroll
    for (int bb = 0; bb < 2; ++bb) {
        int bin = t + bb * 128;
        const unsigned int* row = c32 + bin * 32;
        unsigned int s = 0u;
        #pragma unroll
        for (int k = 0; k < 32; ++k)
            s = __dp4a(row[(lane + k) & 31], 0x01010101u, s);
        hs[bin] = (float)s;
    }
    __syncthreads();

    // ---- clip: redistribute excess above TV uniformly ----
    float h0 = hs[t], h1 = hs[t + 128];
    int eloc = (int)fmaxf(h0 - TV, 0.f) + (int)fmaxf(h1 - TV, 0.f);
    #pragma unroll
    for (int off = 16; off; off >>= 1)
        eloc += __shfl_xor_sync(0xffffffffu, eloc, off);
    if (lane == 0) wsum[warp] = eloc;
    __syncthreads();
    float me = (float)(wsum[0] + wsum[1] + wsum[2] + wsum[3]) * (1.0f / 256.0f);
    cs[t]       = floorf((h0 >= TV) ? (TV + me) : (h0 + me));
    cs[t + 128] = floorf((h1 >= TV) ? (TV + me) : (h1 + me));
    __syncthreads();

    // ---- inclusive scan over 256 bins (warp 0, 8 chunks of 32) ----
    if (warp == 0) {
        float run = 0.f;
        #pragma unroll
        for (int ch = 0; ch < 8; ++ch) {
            float v = cs[ch * 32 + lane];
            #pragma unroll
            for (int off = 1; off < 32; off <<= 1) {
                float n = __shfl_up_sync(0xffffffffu, v, off);
                if (lane >= off) v += n;
            }
            v += run;
            cs[ch * 32 + lane] = v;
            run = __shfl_sync(0xffffffffu, v, 31);
        }
    }
    __syncthreads();

    // ---- map = floor(cdf * 255/16384) & 255 ----
    float* gm = g_maps + (size_t)(b * 64 + blk) * LEVEL;
    #pragma unroll
    for (int bb = 0; bb < 2; ++bb) {
        int bin = t + bb * 128;
        int mi = (int)floorf(cs[bin] * (255.0f / 16384.0f));
        gm[bin] = (float)(mi & 255);
    }
}

// ============================================================================
// Kernel 2: per-pixel bilinear blend of 2x2 block maps
// grid: (16, 16, B) tiles of 64x64; block: (16,16); float4 per thread
// Tiles are 64-aligned so (r,c) interpolation cell is constant per tile.
// ============================================================================
__global__ __launch_bounds__(256) void apply_kernel(const float* __restrict__ img,
                                                    float* __restrict__ out) {
    __shared__ float4 sm[LEVEL];   // packed {lu, lb, ru, rb} per value

    const int tx  = threadIdx.x;   // 0..15
    const int ty  = threadIdx.y;   // 0..15
    const int tid = ty * 16 + tx;
    const int i0  = blockIdx.y * 64;
    const int j0  = blockIdx.x * 64;
    const int b   = blockIdx.z;

    const int r  = (i0 < 64) ? 0 : ((i0 - 64) >> 7);
    const int c  = (j0 < 64) ? 0 : ((j0 - 64) >> 7);
    const int rp = min(r + 1, NBLK - 1);
    const int cp = min(c + 1, NBLK - 1);

    const float* gmb = g_maps + (size_t)b * 64 * LEVEL;
    sm[tid] = make_float4(gmb[(r  * 8 + c ) * LEVEL + tid],
                          gmb[(rp * 8 + c ) * LEVEL + tid],
                          gmb[(r  * 8 + cp) * LEVEL + tid],
                          gmb[(rp * 8 + cp) * LEVEL + tid]);
    __syncthreads();

    const bool  xz  = (r >= NBLK - 1);
    const bool  yz  = (c >= NBLK - 1);
    const float inv = 1.0f / 128.0f;

    const int jbase = j0 + tx * 4;
    float yw[4];
    #pragma unroll
    for (int u = 0; u < 4; ++u)
        yw[u] = yz ? 0.f : (float)(jbase + u - c * 128 - 64) * inv;

    const float* ip = img + (size_t)b * HH * WW;
    float*       op = out + (size_t)b * HH * WW;

    #pragma unroll
    for (int k = 0; k < 4; ++k) {
        const int i = i0 + ty + k * 16;
        const float xw = xz ? 0.f : (float)(i - r * 128 - 64) * inv;
        const float4 p = *reinterpret_cast<const float4*>(ip + (size_t)i * WW + jbase);
        float vals[4] = {p.x, p.y, p.z, p.w};
        float res[4];
        #pragma unroll
        for (int u = 0; u < 4; ++u) {
            const float4 m = sm[(int)vals[u]];
            float a  = m.x + xw * (m.y - m.x);      // blend r -> rp
            float bb = m.z + xw * (m.w - m.z);
            float o  = a + yw[u] * (bb - a);        // blend c -> cp
            res[u] = (float)(((int)o) & 255);       // trunc + %256 (Python semantics)
        }
        *reinterpret_cast<float4*>(op + (size_t)i * WW + jbase) =
            make_float4(res[0], res[1], res[2], res[3]);
    }
}

extern "C" void kernel_launch(void* const* d_in, const int* in_sizes, int n_in,
                              void* d_out, int out_size) {
    const float* img = (const float*)d_in[0];
    float*       out = (float*)d_out;
    const int B = in_sizes[0] / (HH * WW);   // 16
    hist_maps_kernel<<<dim3(NBLK * NBLK, B), 128>>>(img);
    apply_kernel<<<dim3(16, 16, B), dim3(16, 16)>>>(img, out);
}

// round 3
// speedup vs baseline: 1.1360x; 1.1360x over previous
#include <cuda_runtime.h>

#define LEVEL 256
#define NBLK  8
#define HH    1024
#define WW    1024
#define BM    128
#define BN    128
#define TV    640.0f       // (BM*BN)/LEVEL*THRESH

// per-block uint8 mapping tables (B=16, 64 blocks, 256 bins)
__device__ unsigned char g_maps8[16 * NBLK * NBLK * LEVEL];

// ============================================================================
// Kernel 1: per-block histogram (atomic-free byte counters) + clip + CDF->map
// grid: (64, B), block: 128 threads
// ============================================================================
__global__ __launch_bounds__(128) void hist_maps_kernel(const float* __restrict__ img) {
    // counters: [bin][byte 0..127], byte index = lane*4 + warp
    // word index = bin*32 + lane  ->  bank = lane  (conflict-free)
    __shared__ unsigned char cnt[LEVEL * 128];   // 32 KB
    __shared__ float hs[LEVEL];
    __shared__ float cs[LEVEL];
    __shared__ int   wsum[4];

    const int t    = threadIdx.x;
    const int lane = t & 31;
    const int warp = t >> 5;
    const int blk  = blockIdx.x;
    const int b    = blockIdx.y;
    const int bi   = blk >> 3, bj = blk & 7;

    unsigned int* c32 = reinterpret_cast<unsigned int*>(cnt);
    #pragma unroll
    for (int k = 0; k < 64; ++k) c32[t + k * 128] = 0u;
    __syncthreads();

    // ---- accumulate 128x128 region (float4 loads) ----
    const float* base = img + ((size_t)b * HH + (size_t)bi * BM) * WW + bj * BN;
    const int boff = lane * 4 + warp;
    #pragma unroll 8
    for (int k = 0; k < 32; ++k) {
        int idx = k * 128 + t;
        int row = idx >> 5;
        int c4  = idx & 31;
        float4 p = *reinterpret_cast<const float4*>(base + (size_t)row * WW + c4 * 4);
        cnt[((int)p.x) * 128 + boff]++;
        cnt[((int)p.y) * 128 + boff]++;
        cnt[((int)p.z) * 128 + boff]++;
        cnt[((int)p.w) * 128 + boff]++;
    }
    __syncthreads();

    // ---- reduce 128 bytes per bin via dp4a (lane-rotated, conflict-free) ----
    #pragma unroll
    for (int bb = 0; bb < 2; ++bb) {
        int bin = t + bb * 128;
        const unsigned int* row = c32 + bin * 32;
        unsigned int s = 0u;
        #pragma unroll
        for (int k = 0; k < 32; ++k)
            s = __dp4a(row[(lane + k) & 31], 0x01010101u, s);
        hs[bin] = (float)s;
    }
    __syncthreads();

    // ---- clip: redistribute excess above TV uniformly ----
    float h0 = hs[t], h1 = hs[t + 128];
    int eloc = (int)fmaxf(h0 - TV, 0.f) + (int)fmaxf(h1 - TV, 0.f);
    #pragma unroll
    for (int off = 16; off; off >>= 1)
        eloc += __shfl_xor_sync(0xffffffffu, eloc, off);
    if (lane == 0) wsum[warp] = eloc;
    __syncthreads();
    float me = (float)(wsum[0] + wsum[1] + wsum[2] + wsum[3]) * (1.0f / 256.0f);
    cs[t]       = floorf((h0 >= TV) ? (TV + me) : (h0 + me));
    cs[t + 128] = floorf((h1 >= TV) ? (TV + me) : (h1 + me));
    __syncthreads();

    // ---- inclusive scan over 256 bins (warp 0) ----
    if (warp == 0) {
        float run = 0.f;
        #pragma unroll
        for (int ch = 0; ch < 8; ++ch) {
            float v = cs[ch * 32 + lane];
            #pragma unroll
            for (int off = 1; off < 32; off <<= 1) {
                float n = __shfl_up_sync(0xffffffffu, v, off);
                if (lane >= off) v += n;
            }
            v += run;
            cs[ch * 32 + lane] = v;
            run = __shfl_sync(0xffffffffu, v, 31);
        }
    }
    __syncthreads();

    // ---- map = floor(cdf * 255/16384) & 255, packed uchar4 store ----
    if (t < 64) {
        unsigned char* gm = g_maps8 + (size_t)(b * 64 + blk) * LEVEL;
        uchar4 q;
        q.x = (unsigned char)(((int)floorf(cs[4 * t + 0] * (255.0f / 16384.0f))) & 255);
        q.y = (unsigned char)(((int)floorf(cs[4 * t + 1] * (255.0f / 16384.0f))) & 255);
        q.z = (unsigned char)(((int)floorf(cs[4 * t + 2] * (255.0f / 16384.0f))) & 255);
        q.w = (unsigned char)(((int)floorf(cs[4 * t + 3] * (255.0f / 16384.0f))) & 255);
        *reinterpret_cast<uchar4*>(gm + 4 * t) = q;
    }
}

// ============================================================================
// Kernel 2: bilinear blend. Packed u32 map table, replicated 32x (per bank):
// sm[v*32 + lane] -> bank == lane, structurally conflict-free LDS.32.
// grid: (16, 16, B) tiles of 64x64; block: (16,16); float4 per thread
// ============================================================================
__global__ __launch_bounds__(256) void apply_kernel(const float* __restrict__ img,
                                                    float* __restrict__ out) {
    __shared__ unsigned int sm[LEVEL * 32];   // 32 KB

    const int tx   = threadIdx.x;
    const int ty   = threadIdx.y;
    const int tid  = ty * 16 + tx;
    const int lane = tid & 31;
    const int i0   = blockIdx.y * 64;
    const int j0   = blockIdx.x * 64;
    const int b    = blockIdx.z;

    const int r  = (i0 < 64) ? 0 : ((i0 - 64) >> 7);
    const int c  = (j0 < 64) ? 0 : ((j0 - 64) >> 7);
    const int rp = min(r + 1, NBLK - 1);
    const int cp = min(c + 1, NBLK - 1);

    // build packed word {lu, lb, ru, rb} for value v = tid, replicate to all banks
    {
        const unsigned char* gm = g_maps8 + (size_t)b * 64 * LEVEL;
        unsigned int w = (unsigned int)gm[(r  * 8 + c ) * LEVEL + tid]
                       | ((unsigned int)gm[(rp * 8 + c ) * LEVEL + tid] << 8)
                       | ((unsigned int)gm[(r  * 8 + cp) * LEVEL + tid] << 16)
                       | ((unsigned int)gm[(rp * 8 + cp) * LEVEL + tid] << 24);
        #pragma unroll
        for (int k = 0; k < 32; ++k)
            sm[tid * 32 + ((lane + k) & 31)] = w;   // rotated: conflict-free fill
    }
    __syncthreads();

    const bool  xz  = (r >= NBLK - 1);
    const bool  yz  = (c >= NBLK - 1);
    const float inv = 1.0f / 128.0f;

    const int jbase = j0 + tx * 4;
    float yw[4];
    #pragma unroll
    for (int u = 0; u < 4; ++u)
        yw[u] = yz ? 0.f : (float)(jbase + u - c * 128 - 64) * inv;

    const float* ip = img + (size_t)b * HH * WW;
    float*       op = out + (size_t)b * HH * WW;

    #pragma unroll
    for (int k = 0; k < 4; ++k) {
        const int i = i0 + ty + k * 16;
        const float xw = xz ? 0.f : (float)(i - r * 128 - 64) * inv;
        const float4 p = *reinterpret_cast<const float4*>(ip + (size_t)i * WW + jbase);
        float vals[4] = {p.x, p.y, p.z, p.w};
        float res[4];
        #pragma unroll
        for (int u = 0; u < 4; ++u) {
            const unsigned int m = sm[((int)vals[u]) * 32 + lane];  // bank-conflict-free
            const float lu = (float)(m & 255u);
            const float lb = (float)((m >> 8) & 255u);
            const float ru = (float)((m >> 16) & 255u);
            const float rb = (float)(m >> 24);
            float a  = lu + xw * (lb - lu);
            float bb = ru + xw * (rb - ru);
            float o  = a + yw[u] * (bb - a);
            res[u] = (float)(((int)o) & 255);
        }
        __stcs(reinterpret_cast<float4*>(op + (size_t)i * WW + jbase),
               make_float4(res[0], res[1], res[2], res[3]));
    }
}

extern "C" void kernel_launch(void* const* d_in, const int* in_sizes, int n_in,
                              void* d_out, int out_size) {
    const float* img = (const float*)d_in[0];
    float*       out = (float*)d_out;
    const int B = in_sizes[0] / (HH * WW);   // 16
    hist_maps_kernel<<<dim3(NBLK * NBLK, B), 128>>>(img);
    apply_kernel<<<dim3(16, 16, B), dim3(16, 16)>>>(img, out);
}

// round 4
// speedup vs baseline: 1.2957x; 1.1405x over previous
#include <cuda_runtime.h>

#define LEVEL 256
#define NBLK  8
#define HH    1024
#define WW    1024
#define BM    128
#define BN    128
#define TV    640.0f       // (BM*BN)/LEVEL*THRESH

// per-block uint8 mapping tables (B=16, 64 blocks, 256 bins)
__device__ unsigned char g_maps8[16 * NBLK * NBLK * LEVEL];

// ============================================================================
// Kernel 1: per-block histogram (per-warp u32 smem atomics) + clip + CDF->map
// grid: (64, B), block: 128 threads
// ============================================================================
__global__ __launch_bounds__(128) void hist_maps_kernel(const float* __restrict__ img) {
    __shared__ unsigned int h4[4][LEVEL];   // per-warp histograms, 4 KB
    __shared__ float cs[LEVEL];
    __shared__ int   wsum[4];

    const int t    = threadIdx.x;
    const int lane = t & 31;
    const int warp = t >> 5;
    const int blk  = blockIdx.x;
    const int b    = blockIdx.y;
    const int bi   = blk >> 3, bj = blk & 7;

    // zero 1024 words
    #pragma unroll
    for (int k = 0; k < 8; ++k) ((unsigned int*)h4)[t + k * 128] = 0u;
    __syncthreads();

    // ---- accumulate 128x128 region (float4 loads, per-warp atomic hist) ----
    const float* base = img + ((size_t)b * HH + (size_t)bi * BM) * WW + bj * BN;
    unsigned int* hw = h4[warp];
    #pragma unroll 8
    for (int k = 0; k < 32; ++k) {
        int idx = k * 128 + t;
        int row = idx >> 5;
        int c4  = idx & 31;
        float4 p = *reinterpret_cast<const float4*>(base + (size_t)row * WW + c4 * 4);
        atomicAdd(&hw[(int)p.x], 1u);
        atomicAdd(&hw[(int)p.y], 1u);
        atomicAdd(&hw[(int)p.z], 1u);
        atomicAdd(&hw[(int)p.w], 1u);
    }
    __syncthreads();

    // ---- merge 4 sub-hists; each thread owns bins t and t+128 ----
    float h0 = (float)(h4[0][t]       + h4[1][t]       + h4[2][t]       + h4[3][t]);
    float h1 = (float)(h4[0][t + 128] + h4[1][t + 128] + h4[2][t + 128] + h4[3][t + 128]);

    // ---- clip: redistribute excess above TV uniformly ----
    int eloc = (int)fmaxf(h0 - TV, 0.f) + (int)fmaxf(h1 - TV, 0.f);
    #pragma unroll
    for (int off = 16; off; off >>= 1)
        eloc += __shfl_xor_sync(0xffffffffu, eloc, off);
    if (lane == 0) wsum[warp] = eloc;
    __syncthreads();
    float me = (float)(wsum[0] + wsum[1] + wsum[2] + wsum[3]) * (1.0f / 256.0f);
    cs[t]       = floorf((h0 >= TV) ? (TV + me) : (h0 + me));
    cs[t + 128] = floorf((h1 >= TV) ? (TV + me) : (h1 + me));
    __syncthreads();

    // ---- inclusive scan over 256 bins (warp 0) ----
    if (warp == 0) {
        float run = 0.f;
        #pragma unroll
        for (int ch = 0; ch < 8; ++ch) {
            float v = cs[ch * 32 + lane];
            #pragma unroll
            for (int off = 1; off < 32; off <<= 1) {
                float n = __shfl_up_sync(0xffffffffu, v, off);
                if (lane >= off) v += n;
            }
            v += run;
            cs[ch * 32 + lane] = v;
            run = __shfl_sync(0xffffffffu, v, 31);
        }
    }
    __syncthreads();

    // ---- map = floor(cdf * 255/16384) & 255, packed uchar4 store ----
    if (t < 64) {
        unsigned char* gm = g_maps8 + (size_t)(b * 64 + blk) * LEVEL;
        uchar4 q;
        q.x = (unsigned char)(((int)floorf(cs[4 * t + 0] * (255.0f / 16384.0f))) & 255);
        q.y = (unsigned char)(((int)floorf(cs[4 * t + 1] * (255.0f / 16384.0f))) & 255);
        q.z = (unsigned char)(((int)floorf(cs[4 * t + 2] * (255.0f / 16384.0f))) & 255);
        q.w = (unsigned char)(((int)floorf(cs[4 * t + 3] * (255.0f / 16384.0f))) & 255);
        *reinterpret_cast<uchar4*>(gm + 4 * t) = q;
    }
}

// ============================================================================
// Kernel 2: bilinear blend. Packed u32 map table, replicated 32x (per bank).
// PRMT magic-number unpack: byte b -> float (32768 + b) in one PRMT.
// All FP math exact (verified granularity/magnitude bounds) => bit-exact.
// grid: (16, 16, B) tiles of 64x64; block: (16,16); float4 per thread
// ============================================================================
__global__ __launch_bounds__(256) void apply_kernel(const float* __restrict__ img,
                                                    float* __restrict__ out) {
    __shared__ unsigned int sm[LEVEL * 32];   // 32 KB

    const int tx   = threadIdx.x;
    const int ty   = threadIdx.y;
    const int tid  = ty * 16 + tx;
    const int lane = tid & 31;
    const int i0   = blockIdx.y * 64;
    const int j0   = blockIdx.x * 64;
    const int b    = blockIdx.z;

    const int r  = (i0 < 64) ? 0 : ((i0 - 64) >> 7);
    const int c  = (j0 < 64) ? 0 : ((j0 - 64) >> 7);
    const int rp = min(r + 1, NBLK - 1);
    const int cp = min(c + 1, NBLK - 1);

    // packed word {lu, lb, ru, rb} for value v = tid, replicated to all banks
    {
        const unsigned char* gm = g_maps8 + (size_t)b * 64 * LEVEL;
        unsigned int w = (unsigned int)gm[(r  * 8 + c ) * LEVEL + tid]
                       | ((unsigned int)gm[(rp * 8 + c ) * LEVEL + tid] << 8)
                       | ((unsigned int)gm[(r  * 8 + cp) * LEVEL + tid] << 16)
                       | ((unsigned int)gm[(rp * 8 + cp) * LEVEL + tid] << 24);
        #pragma unroll
        for (int k = 0; k < 32; ++k)
            sm[tid * 32 + ((lane + k) & 31)] = w;
    }
    __syncthreads();

    const bool  xz  = (r >= NBLK - 1);
    const bool  yz  = (c >= NBLK - 1);
    const float inv = 1.0f / 128.0f;

    const int jbase = j0 + tx * 4;
    float yw[4];
    #pragma unroll
    for (int u = 0; u < 4; ++u)
        yw[u] = yz ? 0.f : (float)(jbase + u - c * 128 - 64) * inv;

    const float* ip = img + (size_t)b * HH * WW;
    float*       op = out + (size_t)b * HH * WW;
    const unsigned int* sml = sm + lane;

    #pragma unroll
    for (int k = 0; k < 4; ++k) {
        const int i = i0 + ty + k * 16;
        const float xw = xz ? 0.f : (float)(i - r * 128 - 64) * inv;
        const float4 p = *reinterpret_cast<const float4*>(ip + (size_t)i * WW + jbase);
        float vals[4] = {p.x, p.y, p.z, p.w};
        float res[4];
        #pragma unroll
        for (int u = 0; u < 4; ++u) {
            const unsigned int m = sml[((int)vals[u]) * 32];   // conflict-free LDS
            // magic floats: value = 32768 + byte  (exact; ulp <= 2^-8 here)
            const float lu = __uint_as_float(__byte_perm(m, 0x47000000u, 0x7404));
            const float lb = __uint_as_float(__byte_perm(m, 0x47000000u, 0x7414));
            const float ru = __uint_as_float(__byte_perm(m, 0x47000000u, 0x7424));
            const float rb = __uint_as_float(__byte_perm(m, 0x47000000u, 0x7434));
            const float d1 = lb - lu;                 // exact int diff (magic cancels)
            const float d2 = rb - ru;
            const float a  = fmaf(xw, d1, lu);        // 32768 + a_true, exact
            const float bb = fmaf(xw, d2, ru);        // 32768 + b_true, exact
            const float d3 = bb - a;                  // exact
            const float o  = fmaf(yw[u], d3, a - 32768.0f);   // exact bilinear value
            res[u] = (float)(((int)o) & 255);         // trunc + %256 (Python semantics)
        }
        __stcs(reinterpret_cast<float4*>(op + (size_t)i * WW + jbase),
               make_float4(res[0], res[1], res[2], res[3]));
    }
}

extern "C" void kernel_launch(void* const* d_in, const int* in_sizes, int n_in,
                              void* d_out, int out_size) {
    const float* img = (const float*)d_in[0];
    float*       out = (float*)d_out;
    const int B = in_sizes[0] / (HH * WW);   // 16
    hist_maps_kernel<<<dim3(NBLK * NBLK, B), 128>>>(img);
    apply_kernel<<<dim3(16, 16, B), dim3(16, 16)>>>(img, out);
}